// round 9
// baseline (speedup 1.0000x reference)
#include <cuda_runtime.h>
#include <cuda_fp16.h>
#include <mma.h>
#include <cstdint>
#include <math.h>

using namespace nvcuda;

// Problem shape (fixed by the dataset)
constexpr int NB = 16384;   // batch rows
constexpr int ND = 2048;    // feature dim (K)
constexpr int NH = 512;     // hidden dim
constexpr int NSTAGE = ND / 32;   // 64 k-stages of BK=32

// Scratch (no cudaMalloc allowed)
__device__ float g_ypart[4 * NB];
__device__ float g_l1[NB];
__device__ __align__(128) __half g_w1t_hi[NH * ND];  // W1^T hi (fp16)
__device__ __align__(128) __half g_w1t_lo[NH * ND];  // W1^T residual (fp16)
__device__ __align__(128) __half g_x_hi[(size_t)NB * ND];
__device__ __align__(128) __half g_x_lo[(size_t)NB * ND];

// Dynamic SMEM: 4 pipeline slots of 48KB.
// Within a slot: A_hi 0, A_lo 12288, B_hi 24576, B_lo 36864.
// Tile = 128 rows x 48 halves (96B stride, 64B data + 32B pad).
// Epilogue aliases offset 0 as float ep[128][132] (67584 B).
constexpr int SLOT = 49152;
constexpr int SMEM_DYN = 4 * SLOT;   // 196608

static __device__ __forceinline__ uint32_t smem_u32(const void* p) {
    uint32_t a;
    asm("{ .reg .u64 t; cvta.to.shared.u64 t, %1; cvt.u32.u64 %0, t; }" : "=r"(a) : "l"(p));
    return a;
}

// ============================================================================
// Kernel 0a: transpose + fp16-split W1[K,NH] -> W1T_hi/lo[NH,K]
// ============================================================================
__global__ void prep_w1t(const float* __restrict__ W1)
{
    __shared__ float t[32][33];
    const int k0 = blockIdx.x * 32, n0 = blockIdx.y * 32;
    const int tx = threadIdx.x, ty = threadIdx.y;   // 32 x 8
#pragma unroll
    for (int i = 0; i < 32; i += 8)
        t[ty + i][tx] = W1[(size_t)(k0 + ty + i) * NH + n0 + tx];
    __syncthreads();
#pragma unroll
    for (int i = 0; i < 32; i += 8) {
        float v = t[tx][ty + i];                    // W1[k0+tx][n0+ty+i]
        __half hi = __float2half(v);
        __half lo = __float2half(v - __half2float(hi));
        g_w1t_hi[(size_t)(n0 + ty + i) * ND + k0 + tx] = hi;
        g_w1t_lo[(size_t)(n0 + ty + i) * ND + k0 + tx] = lo;
    }
}

// ============================================================================
// Kernel 0b: fp16-split x -> g_x_hi / g_x_lo  (memory-bound)
// ============================================================================
__global__ void prep_x(const float* __restrict__ x)
{
    size_t i4 = (size_t)blockIdx.x * 256 + threadIdx.x;   // float4 index
    float4 v = ((const float4*)x)[i4];
    __half h0 = __float2half(v.x), h1 = __float2half(v.y);
    __half h2 = __float2half(v.z), h3 = __float2half(v.w);
    __half l0 = __float2half(v.x - __half2float(h0));
    __half l1 = __float2half(v.y - __half2float(h1));
    __half l2 = __float2half(v.z - __half2float(h2));
    __half l3 = __float2half(v.w - __half2float(h3));
    __half2* ph = (__half2*)(g_x_hi + 4 * i4);
    __half2* pl = (__half2*)(g_x_lo + 4 * i4);
    ph[0] = __half2(h0, h1); ph[1] = __half2(h2, h3);
    pl[0] = __half2(l0, l1); pl[1] = __half2(l2, l3);
}

// ============================================================================
// Kernel 1: split-fp16 wmma GEMM  h = x @ W1  (3 MMAs per fp32 MMA) with fused
//           bias+ReLU+(.W2) epilogue -> g_ypart[nt][batch row].
// CTA: BM=128 batch x BN=128 hidden, BK=32, 8 warps (2m x 4n), warp m64n32.
// 4-stage cp.async pipeline, occ 1 (no reg cap -> no spills).
// ============================================================================
__global__ __launch_bounds__(256, 1) void gemm_mma(
    const float* __restrict__ b1v, const float* __restrict__ W2v)
{
    extern __shared__ __align__(128) char smc[];
    __shared__ float b1s[128], w2s[128];
    __shared__ float red2[256];

    const int tid = threadIdx.x;
    const int wid = tid >> 5;
    const int nt = blockIdx.x;          // 0..3   hidden tile (fastest -> L2 x reuse)
    const int mt = blockIdx.y;          // 0..127 batch tile
    const int n0 = nt * 128;
    const int m0 = mt * 128;
    const int wm = wid & 1;             // warp m block (64)
    const int wn = wid >> 1;            // warp n block (32)
    const uint32_t smb = smem_u32(smc);

    if (tid < 128) { b1s[tid] = b1v[n0 + tid]; w2s[tid] = W2v[n0 + tid]; }

    wmma::fragment<wmma::accumulator, 16, 16, 16, float> acc[4][2];
#pragma unroll
    for (int i = 0; i < 4; i++)
#pragma unroll
        for (int j = 0; j < 2; j++) wmma::fill_fragment(acc[i][j], 0.0f);

    // ---- async stage loader: 2048 x 16B chunks per stage, 8 per thread ----
    auto issue = [&](int s) {
        const int slot = s & 3;
        const int k0 = s * 32;
#pragma unroll
        for (int i = 0; i < 8; i++) {
            int ch = tid + 256 * i;
            int isB = ch >> 10;
            int c2 = ch & 1023;
            int split = c2 >> 9;
            int rc = c2 & 511;
            int r = rc >> 2, q = rc & 3;
            const __half* gbase =
                isB ? (split ? g_w1t_lo : g_w1t_hi) : (split ? g_x_lo : g_x_hi);
            int row0 = isB ? n0 : m0;
            const void* gptr = gbase + (size_t)(row0 + r) * ND + k0 + q * 8;
            uint32_t sptr = smb + (uint32_t)(slot * SLOT + isB * 24576 + split * 12288
                                             + r * 96 + q * 16);
            asm volatile("cp.async.cg.shared.global [%0], [%1], 16;"
                         :: "r"(sptr), "l"(gptr));
        }
        asm volatile("cp.async.commit_group;");
    };

    issue(0); issue(1); issue(2);

    for (int s = 0; s < NSTAGE; s++) {
        if (s <= NSTAGE - 3)      asm volatile("cp.async.wait_group 2;");
        else if (s == NSTAGE - 2) asm volatile("cp.async.wait_group 1;");
        else                      asm volatile("cp.async.wait_group 0;");
        __syncthreads();

        const int slot = s & 3;
        const __half* Ah = (const __half*)(smc + slot * SLOT);
        const __half* Al = (const __half*)(smc + slot * SLOT + 12288);
        const __half* Bh = (const __half*)(smc + slot * SLOT + 24576);
        const __half* Bl = (const __half*)(smc + slot * SLOT + 36864);

#pragma unroll
        for (int kk = 0; kk < 2; kk++) {
            wmma::fragment<wmma::matrix_b, 16, 16, 16, __half, wmma::col_major> bh[2], bl[2];
#pragma unroll
            for (int j = 0; j < 2; j++) {
                wmma::load_matrix_sync(bh[j], Bh + (wn * 32 + 16 * j) * 48 + kk * 16, 48);
                wmma::load_matrix_sync(bl[j], Bl + (wn * 32 + 16 * j) * 48 + kk * 16, 48);
            }
#pragma unroll
            for (int i = 0; i < 4; i++) {
                wmma::fragment<wmma::matrix_a, 16, 16, 16, __half, wmma::row_major> ah, al;
                wmma::load_matrix_sync(ah, Ah + (wm * 64 + 16 * i) * 48 + kk * 16, 48);
                wmma::load_matrix_sync(al, Al + (wm * 64 + 16 * i) * 48 + kk * 16, 48);
#pragma unroll
                for (int j = 0; j < 2; j++) {
                    wmma::mma_sync(acc[i][j], ah, bh[j], acc[i][j]);
                    wmma::mma_sync(acc[i][j], ah, bl[j], acc[i][j]);
                    wmma::mma_sync(acc[i][j], al, bh[j], acc[i][j]);
                }
            }
        }
        __syncthreads();
        if (s + 3 < NSTAGE) issue(s + 3);
    }

    // ---- epilogue: h -> relu(h+b1)*W2, reduce over this CTA's 128 hidden cols
    float* ep = (float*)smc;   // [128][132], aliases stage buffers (all loads/MMAs done)
#pragma unroll
    for (int i = 0; i < 4; i++)
#pragma unroll
        for (int j = 0; j < 2; j++)
            wmma::store_matrix_sync(&ep[(size_t)(wm * 64 + 16 * i) * 132 + wn * 32 + 16 * j],
                                    acc[i][j], 132, wmma::mem_row_major);
    __syncthreads();

    const int row = tid & 127;
    const int half = tid >> 7;
    float p = 0.f;
#pragma unroll 8
    for (int n = half * 64; n < half * 64 + 64; n++)
        p += fmaxf(ep[(size_t)row * 132 + n] + b1s[n], 0.f) * w2s[n];
    red2[tid] = p;
    __syncthreads();
    if (tid < 128)
        g_ypart[(size_t)nt * NB + m0 + tid] = red2[tid] + red2[tid + 128];
}

// ============================================================================
// Kernel 2: per-row predictor tail (sigmoid -> sparsity, k) fused with exact
// k-th-smallest |x| radix select, then mask / sparse_x / counts / l1.
// ============================================================================
__global__ __launch_bounds__(256) void select_mask(
    const float* __restrict__ x, const float* __restrict__ b2,
    float* __restrict__ out)
{
    __shared__ unsigned hist[2048];
    __shared__ unsigned buf[2048];
    __shared__ unsigned wsum[8];
    __shared__ unsigned scanbuf[256];
    __shared__ float    fred[256];
    __shared__ unsigned sh_sel, sh_rem, sh_cnt, sh_thr, sh_k;

    const int t = threadIdx.x;
    const int lane = t & 31;
    const int warp = t >> 5;
    const int r = blockIdx.x;
    const float4* xrow = (const float4*)(x + (size_t)r * ND);

    // --- fused predictor tail (thread 0) ---
    if (t == 0) {
        float y = ((g_ypart[r] + g_ypart[NB + r])
                   + (g_ypart[2 * NB + r] + g_ypart[3 * NB + r])) + b2[0];
        float sig = 1.f / (1.f + expf(-y));
        float s = 0.05f + 0.25f * sig;
        out[(size_t)2 * NB * ND + r] = s;                 // sparsity
        float kf = rintf(2048.0f * (1.0f - s));           // half-even, matches jnp.round
        int k = (int)kf;
        if (k < 1) k = 1;
        sh_k = (unsigned)k;
        sh_cnt = 0u;
    }

    float4 xv0 = xrow[t];
    float4 xv1 = xrow[t + 256];
    unsigned u0[4], u1[4];
    u0[0] = __float_as_uint(xv0.x) & 0x7fffffffu;
    u0[1] = __float_as_uint(xv0.y) & 0x7fffffffu;
    u0[2] = __float_as_uint(xv0.z) & 0x7fffffffu;
    u0[3] = __float_as_uint(xv0.w) & 0x7fffffffu;
    u1[0] = __float_as_uint(xv1.x) & 0x7fffffffu;
    u1[1] = __float_as_uint(xv1.y) & 0x7fffffffu;
    u1[2] = __float_as_uint(xv1.z) & 0x7fffffffu;
    u1[3] = __float_as_uint(xv1.w) & 0x7fffffffu;
#pragma unroll
    for (int i = 0; i < 8; i++) hist[t + 256 * i] = 0u;
    __syncthreads();

#pragma unroll
    for (int i = 0; i < 4; i++) atomicAdd(&hist[u0[i] >> 20], 1u);
#pragma unroll
    for (int i = 0; i < 4; i++) atomicAdd(&hist[u1[i] >> 20], 1u);
    __syncthreads();

    const unsigned k = sh_k;

    // Shuffle-based segmented scan: thread t owns bins [8t, 8t+8)
    unsigned loc[8], ssum = 0u;
#pragma unroll
    for (int i = 0; i < 8; i++) { loc[i] = hist[8 * t + i]; ssum += loc[i]; }
    unsigned v = ssum;
#pragma unroll
    for (int off = 1; off < 32; off <<= 1) {
        unsigned n = __shfl_up_sync(0xffffffffu, v, off);
        if (lane >= off) v += n;
    }
    if (lane == 31) wsum[warp] = v;
    __syncthreads();
    unsigned wexcl = 0u;
#pragma unroll
    for (int w = 0; w < 8; w++) wexcl += (w < warp) ? wsum[w] : 0u;
    unsigned incl = wexcl + v;
    unsigned excl = incl - ssum;
    if (excl < k && k <= incl) {
        unsigned c = excl;
#pragma unroll
        for (int i = 0; i < 8; i++) {
            c += loc[i];
            if (c >= k) { sh_sel = 8 * t + i; sh_rem = k - (c - loc[i]); break; }
        }
    }
    __syncthreads();
    const unsigned sel = sh_sel;
    const unsigned rem = sh_rem;

    // Warp-aggregated candidate compaction (buf order irrelevant for rank select)
    unsigned mv[8];
    unsigned nm = 0;
#pragma unroll
    for (int i = 0; i < 4; i++) if ((u0[i] >> 20) == sel) mv[nm++] = u0[i];
#pragma unroll
    for (int i = 0; i < 4; i++) if ((u1[i] >> 20) == sel) mv[nm++] = u1[i];
    unsigned v2 = nm;
#pragma unroll
    for (int off = 1; off < 32; off <<= 1) {
        unsigned n = __shfl_up_sync(0xffffffffu, v2, off);
        if (lane >= off) v2 += n;
    }
    unsigned wtot = __shfl_sync(0xffffffffu, v2, 31);
    unsigned wbase = 0;
    if (lane == 31 && wtot > 0) wbase = atomicAdd(&sh_cnt, wtot);
    wbase = __shfl_sync(0xffffffffu, wbase, 31);
    unsigned base = wbase + v2 - nm;
    for (unsigned j = 0; j < nm; j++) buf[base + j] = mv[j];
    __syncthreads();
    const int m = (int)sh_cnt;

    // Exact rank select among m candidates (rem-th smallest), tie-safe.
    for (int c = t; c < m; c += 256) {
        unsigned vv = buf[c];
        unsigned less = 0u, eq = 0u;
        for (int j = 0; j < m; j++) {
            unsigned w = buf[j];
            less += (w < vv);
            eq   += (w == vv);
        }
        if (less < rem && rem <= less + eq) sh_thr = vv;   // unique writer value
    }
    __syncthreads();
    const unsigned thr = sh_thr;   // exact bit pattern of sorted_abs[k-1]

    // Outputs: sparse_x, mask (strict > threshold), counts, l1
    float4* sp = (float4*)(out + (size_t)r * ND);
    float4* mk = (float4*)(out + (size_t)NB * ND + (size_t)r * ND);
    int cnt = 0;
    float l1 = 0.f;
    {
        float4 spv, mkv;
        bool k0b = u0[0] > thr, k1b = u0[1] > thr, k2b = u0[2] > thr, k3b = u0[3] > thr;
        spv.x = k0b ? xv0.x : 0.f; mkv.x = k0b ? 1.f : 0.f;
        spv.y = k1b ? xv0.y : 0.f; mkv.y = k1b ? 1.f : 0.f;
        spv.z = k2b ? xv0.z : 0.f; mkv.z = k2b ? 1.f : 0.f;
        spv.w = k3b ? xv0.w : 0.f; mkv.w = k3b ? 1.f : 0.f;
        cnt += (int)k0b + (int)k1b + (int)k2b + (int)k3b;
        l1 += (k0b ? fabsf(xv0.x) : 0.f) + (k1b ? fabsf(xv0.y) : 0.f)
            + (k2b ? fabsf(xv0.z) : 0.f) + (k3b ? fabsf(xv0.w) : 0.f);
        sp[t] = spv; mk[t] = mkv;

        k0b = u1[0] > thr; k1b = u1[1] > thr; k2b = u1[2] > thr; k3b = u1[3] > thr;
        spv.x = k0b ? xv1.x : 0.f; mkv.x = k0b ? 1.f : 0.f;
        spv.y = k1b ? xv1.y : 0.f; mkv.y = k1b ? 1.f : 0.f;
        spv.z = k2b ? xv1.z : 0.f; mkv.z = k2b ? 1.f : 0.f;
        spv.w = k3b ? xv1.w : 0.f; mkv.w = k3b ? 1.f : 0.f;
        cnt += (int)k0b + (int)k1b + (int)k2b + (int)k3b;
        l1 += (k0b ? fabsf(xv1.x) : 0.f) + (k1b ? fabsf(xv1.y) : 0.f)
            + (k2b ? fabsf(xv1.z) : 0.f) + (k3b ? fabsf(xv1.w) : 0.f);
        sp[t + 256] = spv; mk[t + 256] = mkv;
    }

    scanbuf[t] = (unsigned)cnt;
    fred[t] = l1;
    __syncthreads();
    for (int off = 128; off > 0; off >>= 1) {
        if (t < off) { scanbuf[t] += scanbuf[t + off]; fred[t] += fred[t + off]; }
        __syncthreads();
    }
    if (t == 0) {
        out[(size_t)2 * NB * ND + NB + r] = (float)scanbuf[0] * (1.f / 2048.f);  // actual_sparsity
        g_l1[r] = fred[0];
    }
}

// ============================================================================
// Kernel 3: deterministic mean of per-row l1 sums -> l1_reg scalar
// ============================================================================
__global__ void l1_reduce(float* __restrict__ out)
{
    __shared__ float sm[1024];
    int t = threadIdx.x;
    float s = 0.f;
    for (int i = t; i < NB; i += 1024) s += g_l1[i];
    sm[t] = s;
    __syncthreads();
    for (int off = 512; off > 0; off >>= 1) {
        if (t < off) sm[t] += sm[t + off];
        __syncthreads();
    }
    if (t == 0) out[(size_t)2 * NB * ND + 2 * NB] = sm[0] * (1.f / (float)NB);
}

// ============================================================================
extern "C" void kernel_launch(void* const* d_in, const int* in_sizes, int n_in,
                              void* d_out, int out_size)
{
    const float* x  = (const float*)d_in[0];
    const float* W1 = (const float*)d_in[1];
    const float* b1 = (const float*)d_in[2];
    const float* W2 = (const float*)d_in[3];
    const float* b2 = (const float*)d_in[4];
    float* out = (float*)d_out;

    cudaFuncSetAttribute(gemm_mma, cudaFuncAttributeMaxDynamicSharedMemorySize, SMEM_DYN);

    prep_w1t<<<dim3(ND / 32, NH / 32), dim3(32, 8)>>>(W1);
    prep_x<<<(int)((size_t)NB * ND / 4 / 256), 256>>>(x);
    gemm_mma<<<dim3(4, NB / 128), 256, SMEM_DYN>>>(b1, W2);
    select_mask<<<NB, 256>>>(x, b2, out);
    l1_reduce<<<1, 1024>>>(out);
}

// round 10
// speedup vs baseline: 1.1200x; 1.1200x over previous
#include <cuda_runtime.h>
#include <cuda_bf16.h>
#include <mma.h>
#include <cstdint>
#include <math.h>

using namespace nvcuda;

// Problem shape (fixed by the dataset)
constexpr int NB = 16384;   // batch rows
constexpr int ND = 2048;    // feature dim (K)
constexpr int NH = 512;     // hidden dim
constexpr int NSTAGE = ND / 32;   // 64 k-stages of BK=32

// Scratch (no cudaMalloc allowed)
__device__ float g_ypart[4 * NB];
__device__ float g_l1[NB];
__device__ __align__(128) __nv_bfloat16 g_w1t_hi[NH * ND];  // W1^T hi (bf16)
__device__ __align__(128) __nv_bfloat16 g_w1t_lo[NH * ND];  // W1^T residual (bf16)
__device__ __align__(128) __nv_bfloat16 g_x_hi[(size_t)NB * ND];
__device__ __align__(128) __nv_bfloat16 g_x_lo[(size_t)NB * ND];

// Dynamic SMEM: A tiles (2 buf x 2 split x 128 x 48 bf16 rows, 96B/row) then B.
//   A(buf,split) at (buf*2+split)*12288, B(buf,split) at 49152 + (buf*2+split)*12288
// Epilogue aliases offset 0 as float ep[128][132] (67584 B).
constexpr int SMEM_DYN = 98304;

static __device__ __forceinline__ uint32_t smem_u32(const void* p) {
    uint32_t a;
    asm("{ .reg .u64 t; cvta.to.shared.u64 t, %1; cvt.u32.u64 %0, t; }" : "=r"(a) : "l"(p));
    return a;
}

// ============================================================================
// Kernel 0a: transpose + bf16-split W1[K,NH] -> W1T_hi/lo[NH,K]
// ============================================================================
__global__ void prep_w1t(const float* __restrict__ W1)
{
    __shared__ float t[32][33];
    const int k0 = blockIdx.x * 32, n0 = blockIdx.y * 32;
    const int tx = threadIdx.x, ty = threadIdx.y;   // 32 x 8
#pragma unroll
    for (int i = 0; i < 32; i += 8)
        t[ty + i][tx] = W1[(size_t)(k0 + ty + i) * NH + n0 + tx];
    __syncthreads();
#pragma unroll
    for (int i = 0; i < 32; i += 8) {
        float v = t[tx][ty + i];                    // W1[k0+tx][n0+ty+i]
        __nv_bfloat16 hi = __float2bfloat16(v);
        __nv_bfloat16 lo = __float2bfloat16(v - __bfloat162float(hi));
        g_w1t_hi[(size_t)(n0 + ty + i) * ND + k0 + tx] = hi;
        g_w1t_lo[(size_t)(n0 + ty + i) * ND + k0 + tx] = lo;
    }
}

// ============================================================================
// Kernel 0b: bf16-split x -> g_x_hi / g_x_lo  (memory-bound)
// ============================================================================
__global__ void prep_x(const float* __restrict__ x)
{
    size_t i4 = (size_t)blockIdx.x * 256 + threadIdx.x;   // float4 index
    float4 v = ((const float4*)x)[i4];
    __nv_bfloat16 h0 = __float2bfloat16(v.x), h1 = __float2bfloat16(v.y);
    __nv_bfloat16 h2 = __float2bfloat16(v.z), h3 = __float2bfloat16(v.w);
    __nv_bfloat16 l0 = __float2bfloat16(v.x - __bfloat162float(h0));
    __nv_bfloat16 l1 = __float2bfloat16(v.y - __bfloat162float(h1));
    __nv_bfloat16 l2 = __float2bfloat16(v.z - __bfloat162float(h2));
    __nv_bfloat16 l3 = __float2bfloat16(v.w - __bfloat162float(h3));
    __nv_bfloat162* ph = (__nv_bfloat162*)(g_x_hi + 4 * i4);
    __nv_bfloat162* pl = (__nv_bfloat162*)(g_x_lo + 4 * i4);
    ph[0] = __nv_bfloat162(h0, h1); ph[1] = __nv_bfloat162(h2, h3);
    pl[0] = __nv_bfloat162(l0, l1); pl[1] = __nv_bfloat162(l2, l3);
}

// ============================================================================
// Kernel 1: split-bf16 wmma GEMM  h = x @ W1  (3 MMAs per fp32 MMA) with fused
//           bias+ReLU+(.W2) epilogue -> g_ypart[nt][batch row].
// CTA: BM=128 batch x BN=128 hidden, BK=32, 8 warps (2m x 4n), warp m64n32.
// 2-stage cp.async pipeline, occ 2 (cross-CTA overlap — measured best, R8).
// ============================================================================
__global__ __launch_bounds__(256, 2) void gemm_mma(
    const float* __restrict__ b1v, const float* __restrict__ W2v)
{
    extern __shared__ __align__(128) char smc[];
    __shared__ float b1s[128], w2s[128];
    __shared__ float red2[256];

    const int tid = threadIdx.x;
    const int wid = tid >> 5;
    const int nt = blockIdx.x;          // 0..3   hidden tile
    const int mt = blockIdx.y;          // 0..127 batch tile
    const int n0 = nt * 128;
    const int m0 = mt * 128;
    const int wm = wid & 1;             // warp m block (64)
    const int wn = wid >> 1;            // warp n block (32)
    const uint32_t smb = smem_u32(smc);

    if (tid < 128) { b1s[tid] = b1v[n0 + tid]; w2s[tid] = W2v[n0 + tid]; }

    wmma::fragment<wmma::accumulator, 16, 16, 16, float> acc[4][2];
#pragma unroll
    for (int i = 0; i < 4; i++)
#pragma unroll
        for (int j = 0; j < 2; j++) wmma::fill_fragment(acc[i][j], 0.0f);

    // ---- async stage loader: 2048 x 16B chunks per stage, 8 per thread ----
    auto issue = [&](int s) {
        const int buf = s & 1;
        const int k0 = s * 32;
#pragma unroll
        for (int i = 0; i < 8; i++) {
            int ch = tid + 256 * i;
            int isB = ch >> 10;
            int c2 = ch & 1023;
            int split = c2 >> 9;
            int rc = c2 & 511;
            int r = rc >> 2, q = rc & 3;
            const __nv_bfloat16* gbase =
                isB ? (split ? g_w1t_lo : g_w1t_hi) : (split ? g_x_lo : g_x_hi);
            int row0 = isB ? n0 : m0;
            const void* gptr = gbase + (size_t)(row0 + r) * ND + k0 + q * 8;
            uint32_t sptr = smb + (uint32_t)(isB * 49152 + (buf * 2 + split) * 12288
                                             + r * 96 + q * 16);
            asm volatile("cp.async.cg.shared.global [%0], [%1], 16;"
                         :: "r"(sptr), "l"(gptr));
        }
        asm volatile("cp.async.commit_group;");
    };

    issue(0);

    for (int s = 0; s < NSTAGE; s++) {
        const int buf = s & 1;
        if (s + 1 < NSTAGE) {
            issue(s + 1);
            asm volatile("cp.async.wait_group 1;");
        } else {
            asm volatile("cp.async.wait_group 0;");
        }
        __syncthreads();

        const __nv_bfloat16* Ah = (const __nv_bfloat16*)(smc + (buf * 2 + 0) * 12288);
        const __nv_bfloat16* Al = (const __nv_bfloat16*)(smc + (buf * 2 + 1) * 12288);
        const __nv_bfloat16* Bh = (const __nv_bfloat16*)(smc + 49152 + (buf * 2 + 0) * 12288);
        const __nv_bfloat16* Bl = (const __nv_bfloat16*)(smc + 49152 + (buf * 2 + 1) * 12288);

#pragma unroll
        for (int kk = 0; kk < 2; kk++) {
            wmma::fragment<wmma::matrix_b, 16, 16, 16, __nv_bfloat16, wmma::col_major> bh[2], bl[2];
#pragma unroll
            for (int j = 0; j < 2; j++) {
                wmma::load_matrix_sync(bh[j], Bh + (wn * 32 + 16 * j) * 48 + kk * 16, 48);
                wmma::load_matrix_sync(bl[j], Bl + (wn * 32 + 16 * j) * 48 + kk * 16, 48);
            }
#pragma unroll
            for (int i = 0; i < 4; i++) {
                wmma::fragment<wmma::matrix_a, 16, 16, 16, __nv_bfloat16, wmma::row_major> ah, al;
                wmma::load_matrix_sync(ah, Ah + (wm * 64 + 16 * i) * 48 + kk * 16, 48);
                wmma::load_matrix_sync(al, Al + (wm * 64 + 16 * i) * 48 + kk * 16, 48);
#pragma unroll
                for (int j = 0; j < 2; j++) {
                    wmma::mma_sync(acc[i][j], ah, bh[j], acc[i][j]);
                    wmma::mma_sync(acc[i][j], ah, bl[j], acc[i][j]);
                    wmma::mma_sync(acc[i][j], al, bh[j], acc[i][j]);
                }
            }
        }
        __syncthreads();
    }

    // ---- epilogue: h -> relu(h+b1)*W2, reduce over this CTA's 128 hidden cols
    float* ep = (float*)smc;   // [128][132], aliases stage buffers (loads done)
#pragma unroll
    for (int i = 0; i < 4; i++)
#pragma unroll
        for (int j = 0; j < 2; j++)
            wmma::store_matrix_sync(&ep[(size_t)(wm * 64 + 16 * i) * 132 + wn * 32 + 16 * j],
                                    acc[i][j], 132, wmma::mem_row_major);
    __syncthreads();

    const int row = tid & 127;
    const int half = tid >> 7;
    float p = 0.f;
#pragma unroll 8
    for (int n = half * 64; n < half * 64 + 64; n++)
        p += fmaxf(ep[(size_t)row * 132 + n] + b1s[n], 0.f) * w2s[n];
    red2[tid] = p;
    __syncthreads();
    if (tid < 128)
        g_ypart[(size_t)nt * NB + m0 + tid] = red2[tid] + red2[tid + 128];
}

// ============================================================================
// Kernel 2: fused predictor tail + exact per-row k-th-smallest |x| radix
// select + mask / sparse_x / actual_sparsity / l1. One 256t CTA per row.
// actual_sparsity derived analytically: count_gt = 2048 - (excl + less + eq).
// ============================================================================
__global__ __launch_bounds__(256) void select_mask(
    const float* __restrict__ x, const float* __restrict__ b2,
    float* __restrict__ out)
{
    __shared__ unsigned hist[2048];
    __shared__ unsigned buf[2048];
    __shared__ unsigned wsum[8];
    __shared__ float    fred[256];
    __shared__ unsigned sh_sel, sh_rem, sh_cnt, sh_thr, sh_k;

    const int t = threadIdx.x;
    const int lane = t & 31;
    const int warp = t >> 5;
    const int r = blockIdx.x;
    const float4* xrow = (const float4*)(x + (size_t)r * ND);

    // --- fused predictor tail (thread 0) ---
    if (t == 0) {
        float y = ((g_ypart[r] + g_ypart[NB + r])
                   + (g_ypart[2 * NB + r] + g_ypart[3 * NB + r])) + b2[0];
        float sig = 1.f / (1.f + expf(-y));
        float s = 0.05f + 0.25f * sig;
        out[(size_t)2 * NB * ND + r] = s;                 // sparsity
        float kf = rintf(2048.0f * (1.0f - s));           // half-even, matches jnp.round
        int k = (int)kf;
        if (k < 1) k = 1;
        sh_k = (unsigned)k;
        sh_cnt = 0u;
    }

    float4 xv0 = xrow[t];
    float4 xv1 = xrow[t + 256];
    unsigned u0[4], u1[4];
    u0[0] = __float_as_uint(xv0.x) & 0x7fffffffu;
    u0[1] = __float_as_uint(xv0.y) & 0x7fffffffu;
    u0[2] = __float_as_uint(xv0.z) & 0x7fffffffu;
    u0[3] = __float_as_uint(xv0.w) & 0x7fffffffu;
    u1[0] = __float_as_uint(xv1.x) & 0x7fffffffu;
    u1[1] = __float_as_uint(xv1.y) & 0x7fffffffu;
    u1[2] = __float_as_uint(xv1.z) & 0x7fffffffu;
    u1[3] = __float_as_uint(xv1.w) & 0x7fffffffu;
#pragma unroll
    for (int i = 0; i < 8; i++) hist[t + 256 * i] = 0u;
    __syncthreads();

#pragma unroll
    for (int i = 0; i < 4; i++) atomicAdd(&hist[u0[i] >> 20], 1u);
#pragma unroll
    for (int i = 0; i < 4; i++) atomicAdd(&hist[u1[i] >> 20], 1u);
    __syncthreads();

    const unsigned k = sh_k;

    // Shuffle-based segmented scan: thread t owns bins [8t, 8t+8)
    unsigned loc[8], ssum = 0u;
#pragma unroll
    for (int i = 0; i < 8; i++) { loc[i] = hist[8 * t + i]; ssum += loc[i]; }
    unsigned v = ssum;
#pragma unroll
    for (int off = 1; off < 32; off <<= 1) {
        unsigned n = __shfl_up_sync(0xffffffffu, v, off);
        if (lane >= off) v += n;
    }
    if (lane == 31) wsum[warp] = v;
    __syncthreads();
    unsigned wexcl = 0u;
#pragma unroll
    for (int w = 0; w < 8; w++) wexcl += (w < warp) ? wsum[w] : 0u;
    unsigned incl = wexcl + v;
    unsigned excl = incl - ssum;
    if (excl < k && k <= incl) {
        unsigned c = excl;
#pragma unroll
        for (int i = 0; i < 8; i++) {
            c += loc[i];
            if (c >= k) { sh_sel = 8 * t + i; sh_rem = k - (c - loc[i]); break; }
        }
    }
    __syncthreads();
    const unsigned sel = sh_sel;
    const unsigned rem = sh_rem;   // rank of threshold inside candidate bin
    const unsigned binexcl = k - rem;   // elements strictly below the bin

    // Warp-aggregated candidate compaction (buf order irrelevant for rank select)
    unsigned mv[8];
    unsigned nm = 0;
#pragma unroll
    for (int i = 0; i < 4; i++) if ((u0[i] >> 20) == sel) mv[nm++] = u0[i];
#pragma unroll
    for (int i = 0; i < 4; i++) if ((u1[i] >> 20) == sel) mv[nm++] = u1[i];
    unsigned v2 = nm;
#pragma unroll
    for (int off = 1; off < 32; off <<= 1) {
        unsigned n = __shfl_up_sync(0xffffffffu, v2, off);
        if (lane >= off) v2 += n;
    }
    unsigned wtot = __shfl_sync(0xffffffffu, v2, 31);
    unsigned wbase = 0;
    if (lane == 31 && wtot > 0) wbase = atomicAdd(&sh_cnt, wtot);
    wbase = __shfl_sync(0xffffffffu, wbase, 31);
    unsigned base = wbase + v2 - nm;
    for (unsigned j = 0; j < nm; j++) buf[base + j] = mv[j];
    __syncthreads();
    const int m = (int)sh_cnt;

    // Exact rank select among m candidates (rem-th smallest), tie-safe.
    // Winner also derives actual_sparsity: count_le = binexcl + less + eq.
    for (int c = t; c < m; c += 256) {
        unsigned vv = buf[c];
        unsigned less = 0u, eq = 0u;
        for (int j = 0; j < m; j++) {
            unsigned w = buf[j];
            less += (w < vv);
            eq   += (w == vv);
        }
        if (less < rem && rem <= less + eq) {
            sh_thr = vv;   // unique value among writers
            out[(size_t)2 * NB * ND + NB + r] =
                (float)(2048u - (binexcl + less + eq)) * (1.f / 2048.f);
        }
    }
    __syncthreads();
    const unsigned thr = sh_thr;   // exact bit pattern of sorted_abs[k-1]

    // Outputs: sparse_x, mask (strict > threshold), l1 (from abs bit patterns)
    float4* sp = (float4*)(out + (size_t)r * ND);
    float4* mk = (float4*)(out + (size_t)NB * ND + (size_t)r * ND);
    float l1 = 0.f;
    {
        float4 spv, mkv;
        bool k0b = u0[0] > thr, k1b = u0[1] > thr, k2b = u0[2] > thr, k3b = u0[3] > thr;
        spv.x = k0b ? xv0.x : 0.f; mkv.x = k0b ? 1.f : 0.f;
        spv.y = k1b ? xv0.y : 0.f; mkv.y = k1b ? 1.f : 0.f;
        spv.z = k2b ? xv0.z : 0.f; mkv.z = k2b ? 1.f : 0.f;
        spv.w = k3b ? xv0.w : 0.f; mkv.w = k3b ? 1.f : 0.f;
        l1 += __uint_as_float(k0b ? u0[0] : 0u) + __uint_as_float(k1b ? u0[1] : 0u)
            + __uint_as_float(k2b ? u0[2] : 0u) + __uint_as_float(k3b ? u0[3] : 0u);
        sp[t] = spv; mk[t] = mkv;

        k0b = u1[0] > thr; k1b = u1[1] > thr; k2b = u1[2] > thr; k3b = u1[3] > thr;
        spv.x = k0b ? xv1.x : 0.f; mkv.x = k0b ? 1.f : 0.f;
        spv.y = k1b ? xv1.y : 0.f; mkv.y = k1b ? 1.f : 0.f;
        spv.z = k2b ? xv1.z : 0.f; mkv.z = k2b ? 1.f : 0.f;
        spv.w = k3b ? xv1.w : 0.f; mkv.w = k3b ? 1.f : 0.f;
        l1 += __uint_as_float(k0b ? u1[0] : 0u) + __uint_as_float(k1b ? u1[1] : 0u)
            + __uint_as_float(k2b ? u1[2] : 0u) + __uint_as_float(k3b ? u1[3] : 0u);
        sp[t + 256] = spv; mk[t + 256] = mkv;
    }

    fred[t] = l1;
    __syncthreads();
    for (int off = 128; off > 0; off >>= 1) {
        if (t < off) fred[t] += fred[t + off];
        __syncthreads();
    }
    if (t == 0) g_l1[r] = fred[0];
}

// ============================================================================
// Kernel 3: deterministic mean of per-row l1 sums -> l1_reg scalar
// ============================================================================
__global__ void l1_reduce(float* __restrict__ out)
{
    __shared__ float sm[1024];
    int t = threadIdx.x;
    float s = 0.f;
    for (int i = t; i < NB; i += 1024) s += g_l1[i];
    sm[t] = s;
    __syncthreads();
    for (int off = 512; off > 0; off >>= 1) {
        if (t < off) sm[t] += sm[t + off];
        __syncthreads();
    }
    if (t == 0) out[(size_t)2 * NB * ND + 2 * NB] = sm[0] * (1.f / (float)NB);
}

// ============================================================================
extern "C" void kernel_launch(void* const* d_in, const int* in_sizes, int n_in,
                              void* d_out, int out_size)
{
    const float* x  = (const float*)d_in[0];
    const float* W1 = (const float*)d_in[1];
    const float* b1 = (const float*)d_in[2];
    const float* W2 = (const float*)d_in[3];
    const float* b2 = (const float*)d_in[4];
    float* out = (float*)d_out;

    cudaFuncSetAttribute(gemm_mma, cudaFuncAttributeMaxDynamicSharedMemorySize, SMEM_DYN);

    prep_w1t<<<dim3(ND / 32, NH / 32), dim3(32, 8)>>>(W1);
    prep_x<<<(int)((size_t)NB * ND / 4 / 256), 256>>>(x);
    gemm_mma<<<dim3(4, NB / 128), 256, SMEM_DYN>>>(b1, W2);
    select_mask<<<NB, 256>>>(x, b2, out);
    l1_reduce<<<1, 1024>>>(out);
}